// round 12
// baseline (speedup 1.0000x reference)
#include <cuda_runtime.h>
#include <cuda_fp16.h>
#include <cstdint>

#define NUM_MEM 4096
#define MEM_DIM 512
#define INP_DIM 1024
#define NQ      32768

// ---------------- scratch (static device globals; no allocs) ----------------
__device__ __half g_kh  [(size_t)NQ * INP_DIM];       // 64 MB
__device__ __half g_memh[(size_t)NUM_MEM * MEM_DIM];  // 4 MB
__device__ __half g_fkw [(size_t)INP_DIM * MEM_DIM];  // 1 MB
__device__ __half g_fvw [(size_t)INP_DIM * MEM_DIM];  // 1 MB
__device__ float  g_keylog[(size_t)NUM_MEM * INP_DIM];// 16 MB
__device__ __half g_key [(size_t)NUM_MEM * INP_DIM];  // 8 MB
__device__ __half g_valT[(size_t)INP_DIM * NUM_MEM];  // 8 MB (val transposed, K-major)
__device__ __half g_S   [(size_t)NQ * NUM_MEM];       // 256 MB (E = exp(logits))
__device__ float  g_rowsum[(size_t)NQ];               // 128 KB (softmax denominators)

// ---------------- helpers ----------------
__device__ __forceinline__ uint32_t smem_u32(const void* p) {
    return (uint32_t)__cvta_generic_to_shared(p);
}
__device__ __forceinline__ void cp_async16(uint32_t dst, const void* src) {
    asm volatile("cp.async.cg.shared.global [%0], [%1], 16;\n" :: "r"(dst), "l"(src) : "memory");
}
__device__ __forceinline__ void cp_commit() {
    asm volatile("cp.async.commit_group;\n" ::: "memory");
}
template<int N> __device__ __forceinline__ void cp_wait() {
    asm volatile("cp.async.wait_group %0;\n" :: "n"(N) : "memory");
}

// ---------------- fp32 -> fp16 convert ----------------
__global__ void f32_to_f16_kernel(const float* __restrict__ in,
                                  __half* __restrict__ out, int n4) {
    int i = blockIdx.x * blockDim.x + threadIdx.x;
    if (i < n4) {
        float4 v = reinterpret_cast<const float4*>(in)[i];
        __half2* o = reinterpret_cast<__half2*>(out) + i * 2;
        o[0] = __floats2half2_rn(v.x, v.y);
        o[1] = __floats2half2_rn(v.z, v.w);
    }
}

__global__ void zero_f32_kernel(float* __restrict__ p, int n) {
    int i = blockIdx.x * blockDim.x + threadIdx.x;
    if (i < n) p[i] = 0.f;
}

// shared tile geometry (R7 winner): BM=128, BN=256, BK=64, 4-stage
#define BBM 128
#define BBN 256
#define BBK 64
#define BSTAGES 4
#define BA_BYTES (BBM * 128)                 // 16 KB
#define BB_BYTES (BBN * 128)                 // 32 KB
#define BSTAGE_BYTES (BA_BYTES + BB_BYTES)   // 48 KB
#define BDSMEM (BSTAGES * BSTAGE_BYTES)      // 192 KB

// =====================================================================
// S GEMM: E = exp(A * B^T), fp16 inputs, FP16 ACCUMULATE (rate experiment),
// fp16 E store + fp32 atomic row sums. R7 pipeline structure.
// =====================================================================
__global__ __launch_bounds__(256, 1)
void gemm_s_f16(const __half* __restrict__ A, const __half* __restrict__ B,
                int K, float* __restrict__ rs, __half* __restrict__ Cout, int ldc)
{
    extern __shared__ __align__(128) char dsm[];
    const uint32_t sbase = smem_u32(dsm);

    const int tid  = threadIdx.x;
    const int lane = tid & 31;
    const int warp = tid >> 5;
    const int wm = warp >> 2;
    const int wn = warp & 3;
    const int bm = blockIdx.y * BBM;
    const int bn = blockIdx.x * BBN;

    uint32_t hacc[4][8][2];   // f16x2 accumulators
#pragma unroll
    for (int i = 0; i < 4; i++)
#pragma unroll
        for (int j = 0; j < 8; j++) { hacc[i][j][0] = 0u; hacc[i][j][1] = 0u; }

    const int KT = K / BBK;

    auto load_tile = [&](int st, int kt) {
        const uint32_t a_s = sbase + st * BSTAGE_BYTES;
        const uint32_t b_s = a_s + BA_BYTES;
        const int kk = kt * BBK;
#pragma unroll
        for (int g = 0; g < 4; g++) {
            int idx = tid + g * 256;
            int r = idx >> 3, c = idx & 7;
            cp_async16(a_s + r * 128 + ((c ^ (r & 7)) << 4),
                       A + (size_t)(bm + r) * K + kk + c * 8);
        }
#pragma unroll
        for (int g = 0; g < 8; g++) {
            int idx = tid + g * 256;
            int r = idx >> 3, c = idx & 7;
            cp_async16(b_s + r * 128 + ((c ^ (r & 7)) << 4),
                       B + (size_t)(bn + r) * K + kk + c * 8);
        }
        cp_commit();
    };

    load_tile(0, 0);
    load_tile(1, 1);
    load_tile(2, 2);
    load_tile(3, 3);

    for (int kt = 0; kt < KT; ++kt) {
        const int st = kt & 3;
        cp_wait<BSTAGES - 1>();
        __syncthreads();

        const uint32_t a_s = sbase + st * BSTAGE_BYTES;
        const uint32_t b_s = a_s + BA_BYTES;

#pragma unroll
        for (int ks = 0; ks < 4; ++ks) {
            uint32_t a[4][4];
#pragma unroll
            for (int mi = 0; mi < 4; mi++) {
                int row = wm * 64 + mi * 16 + (lane & 15);
                int c = ks * 2 + (lane >> 4);
                uint32_t addr = a_s + row * 128 + ((c ^ (row & 7)) << 4);
                asm volatile("ldmatrix.sync.aligned.m8n8.x4.shared.b16 {%0,%1,%2,%3}, [%4];\n"
                             : "=r"(a[mi][0]), "=r"(a[mi][1]), "=r"(a[mi][2]), "=r"(a[mi][3])
                             : "r"(addr));
            }
            uint32_t b[8][2];
#pragma unroll
            for (int nb = 0; nb < 4; nb++) {
                int row = wn * 64 + nb * 16 + (lane & 7) + ((lane >> 4) << 3);
                int c = ks * 2 + ((lane >> 3) & 1);
                uint32_t addr = b_s + row * 128 + ((c ^ (row & 7)) << 4);
                asm volatile("ldmatrix.sync.aligned.m8n8.x4.shared.b16 {%0,%1,%2,%3}, [%4];\n"
                             : "=r"(b[nb * 2][0]), "=r"(b[nb * 2][1]),
                               "=r"(b[nb * 2 + 1][0]), "=r"(b[nb * 2 + 1][1])
                             : "r"(addr));
            }
#pragma unroll
            for (int mi = 0; mi < 4; mi++)
#pragma unroll
                for (int ni = 0; ni < 8; ni++)
                    asm volatile("mma.sync.aligned.m16n8k16.row.col.f16.f16.f16.f16 "
                                 "{%0,%1}, {%2,%3,%4,%5}, {%6,%7}, {%0,%1};\n"
                                 : "+r"(hacc[mi][ni][0]), "+r"(hacc[mi][ni][1])
                                 : "r"(a[mi][0]), "r"(a[mi][1]), "r"(a[mi][2]), "r"(a[mi][3]),
                                   "r"(b[ni][0]), "r"(b[ni][1]));
        }

        __syncthreads();
        if (kt + BSTAGES < KT) load_tile(st, kt + BSTAGES);
    }

    const int gid = lane >> 2, tg = lane & 3;
#pragma unroll
    for (int mi = 0; mi < 4; mi++) {
        int row = bm + wm * 64 + mi * 16 + gid;
        float s_lo = 0.f, s_hi = 0.f;
#pragma unroll
        for (int ni = 0; ni < 8; ni++) {
            int col = bn + wn * 64 + ni * 8 + tg * 2;
            float2 f01 = __half22float2(*reinterpret_cast<__half2*>(&hacc[mi][ni][0]));
            float2 f23 = __half22float2(*reinterpret_cast<__half2*>(&hacc[mi][ni][1]));
            float e0 = __expf(f01.x), e1 = __expf(f01.y);
            float e2 = __expf(f23.x), e3 = __expf(f23.y);
            s_lo += e0 + e1;
            s_hi += e2 + e3;
            *reinterpret_cast<__half2*>(&Cout[(size_t)row * ldc + col]) =
                __floats2half2_rn(e0, e1);
            *reinterpret_cast<__half2*>(&Cout[(size_t)(row + 8) * ldc + col]) =
                __floats2half2_rn(e2, e3);
        }
        s_lo += __shfl_xor_sync(0xffffffffu, s_lo, 1);
        s_lo += __shfl_xor_sync(0xffffffffu, s_lo, 2);
        s_hi += __shfl_xor_sync(0xffffffffu, s_hi, 1);
        s_hi += __shfl_xor_sync(0xffffffffu, s_hi, 2);
        if (tg == 0) {
            atomicAdd(&rs[row], s_lo);
            atomicAdd(&rs[row + 8], s_hi);
        }
    }
}

// =====================================================================
// Out GEMM: C = (A * B^T) / rs[row], fp16 inputs, fp32 accum, fp32 store.
// R7 pipeline structure (winner).
// =====================================================================
__global__ __launch_bounds__(256, 1)
void gemm_out(const __half* __restrict__ A, const __half* __restrict__ B,
              int K, const float* __restrict__ rs, float* __restrict__ Cout, int ldc)
{
    extern __shared__ __align__(128) char dsm[];
    const uint32_t sbase = smem_u32(dsm);

    const int tid  = threadIdx.x;
    const int lane = tid & 31;
    const int warp = tid >> 5;
    const int wm = warp >> 2;
    const int wn = warp & 3;
    const int bm = blockIdx.y * BBM;
    const int bn = blockIdx.x * BBN;

    float acc[4][8][4];
#pragma unroll
    for (int i = 0; i < 4; i++)
#pragma unroll
        for (int j = 0; j < 8; j++)
#pragma unroll
            for (int q = 0; q < 4; q++) acc[i][j][q] = 0.f;

    const int KT = K / BBK;

    auto load_tile = [&](int st, int kt) {
        const uint32_t a_s = sbase + st * BSTAGE_BYTES;
        const uint32_t b_s = a_s + BA_BYTES;
        const int kk = kt * BBK;
#pragma unroll
        for (int g = 0; g < 4; g++) {
            int idx = tid + g * 256;
            int r = idx >> 3, c = idx & 7;
            cp_async16(a_s + r * 128 + ((c ^ (r & 7)) << 4),
                       A + (size_t)(bm + r) * K + kk + c * 8);
        }
#pragma unroll
        for (int g = 0; g < 8; g++) {
            int idx = tid + g * 256;
            int r = idx >> 3, c = idx & 7;
            cp_async16(b_s + r * 128 + ((c ^ (r & 7)) << 4),
                       B + (size_t)(bn + r) * K + kk + c * 8);
        }
        cp_commit();
    };

    load_tile(0, 0);
    load_tile(1, 1);
    load_tile(2, 2);
    load_tile(3, 3);

    for (int kt = 0; kt < KT; ++kt) {
        const int st = kt & 3;
        cp_wait<BSTAGES - 1>();
        __syncthreads();

        const uint32_t a_s = sbase + st * BSTAGE_BYTES;
        const uint32_t b_s = a_s + BA_BYTES;

#pragma unroll
        for (int ks = 0; ks < 4; ++ks) {
            uint32_t a[4][4];
#pragma unroll
            for (int mi = 0; mi < 4; mi++) {
                int row = wm * 64 + mi * 16 + (lane & 15);
                int c = ks * 2 + (lane >> 4);
                uint32_t addr = a_s + row * 128 + ((c ^ (row & 7)) << 4);
                asm volatile("ldmatrix.sync.aligned.m8n8.x4.shared.b16 {%0,%1,%2,%3}, [%4];\n"
                             : "=r"(a[mi][0]), "=r"(a[mi][1]), "=r"(a[mi][2]), "=r"(a[mi][3])
                             : "r"(addr));
            }
            uint32_t b[8][2];
#pragma unroll
            for (int nb = 0; nb < 4; nb++) {
                int row = wn * 64 + nb * 16 + (lane & 7) + ((lane >> 4) << 3);
                int c = ks * 2 + ((lane >> 3) & 1);
                uint32_t addr = b_s + row * 128 + ((c ^ (row & 7)) << 4);
                asm volatile("ldmatrix.sync.aligned.m8n8.x4.shared.b16 {%0,%1,%2,%3}, [%4];\n"
                             : "=r"(b[nb * 2][0]), "=r"(b[nb * 2][1]),
                               "=r"(b[nb * 2 + 1][0]), "=r"(b[nb * 2 + 1][1])
                             : "r"(addr));
            }
#pragma unroll
            for (int mi = 0; mi < 4; mi++)
#pragma unroll
                for (int ni = 0; ni < 8; ni++)
                    asm volatile("mma.sync.aligned.m16n8k16.row.col.f32.f16.f16.f32 "
                                 "{%0,%1,%2,%3}, {%4,%5,%6,%7}, {%8,%9}, {%0,%1,%2,%3};\n"
                                 : "+f"(acc[mi][ni][0]), "+f"(acc[mi][ni][1]),
                                   "+f"(acc[mi][ni][2]), "+f"(acc[mi][ni][3])
                                 : "r"(a[mi][0]), "r"(a[mi][1]), "r"(a[mi][2]), "r"(a[mi][3]),
                                   "r"(b[ni][0]), "r"(b[ni][1]));
        }

        __syncthreads();
        if (kt + BSTAGES < KT) load_tile(st, kt + BSTAGES);
    }

    const int gid = lane >> 2, tg = lane & 3;
#pragma unroll
    for (int mi = 0; mi < 4; mi++) {
        int row = bm + wm * 64 + mi * 16 + gid;
        float inv_lo = 1.f / __ldg(&rs[row]);
        float inv_hi = 1.f / __ldg(&rs[row + 8]);
#pragma unroll
        for (int ni = 0; ni < 8; ni++) {
            int col = bn + wn * 64 + ni * 8 + tg * 2;
            Cout[(size_t)row * ldc + col]           = acc[mi][ni][0] * inv_lo;
            Cout[(size_t)row * ldc + col + 1]       = acc[mi][ni][1] * inv_lo;
            Cout[(size_t)(row + 8) * ldc + col]     = acc[mi][ni][2] * inv_hi;
            Cout[(size_t)(row + 8) * ldc + col + 1] = acc[mi][ni][3] * inv_hi;
        }
    }
}

// ---------------- generic fp16 TN GEMM (mma.sync, f32 acc) for the prep GEMMs ------------
#define GBM 128
#define GBN 128
#define GBK 32
#define SSTR 48

__global__ __launch_bounds__(256)
void gemm_tn(const __half* __restrict__ A, const __half* __restrict__ B,
             int M, int N, int K, const float* __restrict__ bias, int mode,
             void* __restrict__ Cout, int ldc)
{
    __shared__ __half sA[2][GBM * SSTR];
    __shared__ __half sB[2][GBN * SSTR];

    const int tid  = threadIdx.x;
    const int lane = tid & 31;
    const int warp = tid >> 5;
    const int wm = warp >> 1;
    const int wn = warp & 1;
    const int bm = blockIdx.y * GBM;
    const int bn = blockIdx.x * GBN;

    const int c0 = tid, c1 = tid + 256;
    const int r0 = c0 >> 2, cc0 = (c0 & 3) * 8;
    const int r1 = c1 >> 2, cc1 = (c1 & 3) * 8;

    float acc[2][8][4];
#pragma unroll
    for (int i = 0; i < 2; i++)
#pragma unroll
        for (int j = 0; j < 8; j++)
#pragma unroll
            for (int q = 0; q < 4; q++) acc[i][j][q] = 0.f;

    const int KT = K / GBK;
    {
        cp_async16(smem_u32(&sA[0][r0 * SSTR + cc0]), A + (size_t)(bm + r0) * K + cc0);
        cp_async16(smem_u32(&sA[0][r1 * SSTR + cc1]), A + (size_t)(bm + r1) * K + cc1);
        cp_async16(smem_u32(&sB[0][r0 * SSTR + cc0]), B + (size_t)(bn + r0) * K + cc0);
        cp_async16(smem_u32(&sB[0][r1 * SSTR + cc1]), B + (size_t)(bn + r1) * K + cc1);
        cp_commit();
    }

    for (int kt = 0; kt < KT; ++kt) {
        const int buf = kt & 1;
        if (kt + 1 < KT) {
            const int k0 = (kt + 1) * GBK;
            const int nb = buf ^ 1;
            cp_async16(smem_u32(&sA[nb][r0 * SSTR + cc0]), A + (size_t)(bm + r0) * K + k0 + cc0);
            cp_async16(smem_u32(&sA[nb][r1 * SSTR + cc1]), A + (size_t)(bm + r1) * K + k0 + cc1);
            cp_async16(smem_u32(&sB[nb][r0 * SSTR + cc0]), B + (size_t)(bn + r0) * K + k0 + cc0);
            cp_async16(smem_u32(&sB[nb][r1 * SSTR + cc1]), B + (size_t)(bn + r1) * K + k0 + cc1);
            cp_commit();
            cp_wait<1>();
        } else {
            cp_wait<0>();
        }
        __syncthreads();

#pragma unroll
        for (int ks = 0; ks < 2; ++ks) {
            uint32_t a[2][4];
#pragma unroll
            for (int mi = 0; mi < 2; mi++) {
                uint32_t addr = smem_u32(&sA[buf][(wm * 32 + mi * 16 + (lane & 15)) * SSTR
                                                  + ks * 16 + (lane >> 4) * 8]);
                asm volatile("ldmatrix.sync.aligned.m8n8.x4.shared.b16 {%0,%1,%2,%3}, [%4];\n"
                             : "=r"(a[mi][0]), "=r"(a[mi][1]), "=r"(a[mi][2]), "=r"(a[mi][3])
                             : "r"(addr));
            }
            uint32_t b[8][2];
#pragma unroll
            for (int nb2 = 0; nb2 < 4; nb2++) {
                int nrow = wn * 64 + nb2 * 16 + (lane & 7) + ((lane >> 4) << 3);
                int kcol = ks * 16 + (((lane >> 3) & 1) << 3);
                uint32_t addr = smem_u32(&sB[buf][nrow * SSTR + kcol]);
                asm volatile("ldmatrix.sync.aligned.m8n8.x4.shared.b16 {%0,%1,%2,%3}, [%4];\n"
                             : "=r"(b[nb2 * 2][0]), "=r"(b[nb2 * 2][1]),
                               "=r"(b[nb2 * 2 + 1][0]), "=r"(b[nb2 * 2 + 1][1])
                             : "r"(addr));
            }
#pragma unroll
            for (int mi = 0; mi < 2; mi++)
#pragma unroll
                for (int ni = 0; ni < 8; ni++)
                    asm volatile("mma.sync.aligned.m16n8k16.row.col.f32.f16.f16.f32 "
                                 "{%0,%1,%2,%3}, {%4,%5,%6,%7}, {%8,%9}, {%0,%1,%2,%3};\n"
                                 : "+f"(acc[mi][ni][0]), "+f"(acc[mi][ni][1]),
                                   "+f"(acc[mi][ni][2]), "+f"(acc[mi][ni][3])
                                 : "r"(a[mi][0]), "r"(a[mi][1]), "r"(a[mi][2]), "r"(a[mi][3]),
                                   "r"(b[ni][0]), "r"(b[ni][1]));
        }
        __syncthreads();
    }

    const int gid = lane >> 2, tg = lane & 3;
#pragma unroll
    for (int mi = 0; mi < 2; mi++) {
#pragma unroll
        for (int ni = 0; ni < 8; ni++) {
            int row = bm + wm * 32 + mi * 16 + gid;
            int col = bn + wn * 64 + ni * 8 + tg * 2;
            float v0 = acc[mi][ni][0], v1 = acc[mi][ni][1];
            float v2 = acc[mi][ni][2], v3 = acc[mi][ni][3];
            if (mode == 1) {
                float* C = (float*)Cout;
                float b0 = bias ? bias[col] : 0.f;
                float b1 = bias ? bias[col + 1] : 0.f;
                C[(size_t)row * ldc + col]           = v0 + b0;
                C[(size_t)row * ldc + col + 1]       = v1 + b1;
                C[(size_t)(row + 8) * ldc + col]     = v2 + b0;
                C[(size_t)(row + 8) * ldc + col + 1] = v3 + b1;
            } else {  // mode 2: relu(C + bias), transposed fp16 store
                __half* C = (__half*)Cout;
                float b0 = bias[col], b1 = bias[col + 1];
                C[(size_t)col * ldc + row]           = __float2half(fmaxf(v0 + b0, 0.f));
                C[(size_t)(col + 1) * ldc + row]     = __float2half(fmaxf(v1 + b1, 0.f));
                C[(size_t)col * ldc + row + 8]       = __float2half(fmaxf(v2 + b0, 0.f));
                C[(size_t)(col + 1) * ldc + row + 8] = __float2half(fmaxf(v3 + b1, 0.f));
            }
        }
    }
}

// ---------------- block reduction helpers ----------------
__device__ __forceinline__ float block_reduce_max(float v, float* sred) {
#pragma unroll
    for (int o = 16; o > 0; o >>= 1) v = fmaxf(v, __shfl_xor_sync(0xffffffffu, v, o));
    if ((threadIdx.x & 31) == 0) sred[threadIdx.x >> 5] = v;
    __syncthreads();
    if (threadIdx.x == 0) {
        float m = sred[0];
        for (int w = 1; w < (int)(blockDim.x >> 5); w++) m = fmaxf(m, sred[w]);
        sred[0] = m;
    }
    __syncthreads();
    float r = sred[0];
    __syncthreads();
    return r;
}
__device__ __forceinline__ float block_reduce_sum(float v, float* sred) {
#pragma unroll
    for (int o = 16; o > 0; o >>= 1) v += __shfl_xor_sync(0xffffffffu, v, o);
    if ((threadIdx.x & 31) == 0) sred[threadIdx.x >> 5] = v;
    __syncthreads();
    if (threadIdx.x == 0) {
        float s = sred[0];
        for (int w = 1; w < (int)(blockDim.x >> 5); w++) s += sred[w];
        sred[0] = s;
    }
    __syncthreads();
    float r = sred[0];
    __syncthreads();
    return r;
}

// ---------------- softmax: fp32 logits row -> fp16 (key derivation) ----------------
__global__ __launch_bounds__(256)
void softmax_f32_f16(const float* __restrict__ in, __half* __restrict__ out, int ncol) {
    __shared__ float sred[8];
    const float* x = in + (size_t)blockIdx.x * ncol;
    __half* o = out + (size_t)blockIdx.x * ncol;
    float m = -1e30f;
    for (int i = threadIdx.x; i < ncol; i += blockDim.x) m = fmaxf(m, x[i]);
    m = block_reduce_max(m, sred);
    float s = 0.f;
    for (int i = threadIdx.x; i < ncol; i += blockDim.x) s += __expf(x[i] - m);
    s = block_reduce_sum(s, sred);
    float inv = 1.f / s;
    for (int i = threadIdx.x; i < ncol; i += blockDim.x)
        o[i] = __float2half(__expf(x[i] - m) * inv);
}

// ---------------- launch ----------------
extern "C" void kernel_launch(void* const* d_in, const int* in_sizes, int n_in,
                              void* d_out, int out_size) {
    const float* k    = (const float*)d_in[0];
    const float* mem  = (const float*)d_in[1];
    const float* fk_w = (const float*)d_in[2];
    const float* fk_b = (const float*)d_in[3];
    const float* fv_w = (const float*)d_in[4];
    const float* fv_b = (const float*)d_in[5];
    float* out = (float*)d_out;

    void *p_kh, *p_memh, *p_fkw, *p_fvw, *p_keylog, *p_key, *p_valT, *p_S, *p_rs;
    cudaGetSymbolAddress(&p_kh, g_kh);
    cudaGetSymbolAddress(&p_memh, g_memh);
    cudaGetSymbolAddress(&p_fkw, g_fkw);
    cudaGetSymbolAddress(&p_fvw, g_fvw);
    cudaGetSymbolAddress(&p_keylog, g_keylog);
    cudaGetSymbolAddress(&p_key, g_key);
    cudaGetSymbolAddress(&p_valT, g_valT);
    cudaGetSymbolAddress(&p_S, g_S);
    cudaGetSymbolAddress(&p_rs, g_rowsum);

    __half* kh     = (__half*)p_kh;
    __half* memh   = (__half*)p_memh;
    __half* fkwh   = (__half*)p_fkw;
    __half* fvwh   = (__half*)p_fvw;
    float*  keylog = (float*)p_keylog;
    __half* keyh   = (__half*)p_key;
    __half* valT   = (__half*)p_valT;
    __half* S      = (__half*)p_S;
    float*  rowsum = (float*)p_rs;

    cudaFuncSetAttribute(gemm_s_f16, cudaFuncAttributeMaxDynamicSharedMemorySize, BDSMEM);
    cudaFuncSetAttribute(gemm_out, cudaFuncAttributeMaxDynamicSharedMemorySize, BDSMEM);

    // converts + rowsum zero
    {
        int n4 = NQ * INP_DIM / 4;
        f32_to_f16_kernel<<<(n4 + 255) / 256, 256>>>(k, kh, n4);
        n4 = NUM_MEM * MEM_DIM / 4;
        f32_to_f16_kernel<<<(n4 + 255) / 256, 256>>>(mem, memh, n4);
        n4 = INP_DIM * MEM_DIM / 4;
        f32_to_f16_kernel<<<(n4 + 255) / 256, 256>>>(fk_w, fkwh, n4);
        f32_to_f16_kernel<<<(n4 + 255) / 256, 256>>>(fv_w, fvwh, n4);
        zero_f32_kernel<<<NQ / 256, 256>>>(rowsum, NQ);
    }

    // prep: key logits (fp32 + bias), val = relu -> transposed fp16
    {
        dim3 grid(INP_DIM / GBN, NUM_MEM / GBM);
        gemm_tn<<<grid, 256>>>(memh, fkwh, NUM_MEM, INP_DIM, MEM_DIM, fk_b, 1, keylog, INP_DIM);
        gemm_tn<<<grid, 256>>>(memh, fvwh, NUM_MEM, INP_DIM, MEM_DIM, fv_b, 2, valT, NUM_MEM);
    }
    softmax_f32_f16<<<NUM_MEM, 256>>>(keylog, keyh, INP_DIM);

    // E = exp(k @ key^T) [32768, 4096] + row sums  (fp16 accumulate)
    {
        dim3 grid(NUM_MEM / BBN, NQ / BBM);   // (16, 256)
        gemm_s_f16<<<grid, 256, BDSMEM>>>(kh, keyh, INP_DIM, rowsum, S, NUM_MEM);
    }

    // out = (E @ valT^T) / rowsum   [32768, 1024]  (fp32 accumulate)
    {
        dim3 grid(INP_DIM / BBN, NQ / BBM);   // (4, 256)
        gemm_out<<<grid, 256, BDSMEM>>>(S, valT, NUM_MEM, rowsum, out, INP_DIM);
    }
}

// round 15
// speedup vs baseline: 1.0225x; 1.0225x over previous
#include <cuda_runtime.h>
#include <cuda_fp16.h>
#include <cstdint>

#define NUM_MEM 4096
#define MEM_DIM 512
#define INP_DIM 1024
#define NQ      32768

// ---------------- scratch (static device globals; no allocs) ----------------
__device__ __half g_kh  [(size_t)NQ * INP_DIM];       // 64 MB
__device__ __half g_memh[(size_t)NUM_MEM * MEM_DIM];  // 4 MB
__device__ __half g_fkw [(size_t)INP_DIM * MEM_DIM];  // 1 MB
__device__ __half g_fvw [(size_t)INP_DIM * MEM_DIM];  // 1 MB
__device__ float  g_keylog[(size_t)NUM_MEM * INP_DIM];// 16 MB
__device__ __half g_key [(size_t)NUM_MEM * INP_DIM];  // 8 MB
__device__ __half g_valT[(size_t)INP_DIM * NUM_MEM];  // 8 MB (val transposed, K-major)
__device__ __half g_S   [(size_t)NQ * NUM_MEM];       // 256 MB (E = exp(logits))
__device__ float  g_rowsum[(size_t)NQ];               // 128 KB (softmax denominators)

// ---------------- helpers ----------------
__device__ __forceinline__ uint32_t smem_u32(const void* p) {
    return (uint32_t)__cvta_generic_to_shared(p);
}
__device__ __forceinline__ void cp_async16(uint32_t dst, const void* src) {
    asm volatile("cp.async.cg.shared.global [%0], [%1], 16;\n" :: "r"(dst), "l"(src) : "memory");
}
__device__ __forceinline__ void cp_commit() {
    asm volatile("cp.async.commit_group;\n" ::: "memory");
}
template<int N> __device__ __forceinline__ void cp_wait() {
    asm volatile("cp.async.wait_group %0;\n" :: "n"(N) : "memory");
}

// ---------------- fused converts (k, mem, fk_w, fv_w) + rowsum zero, one launch --------
// region sizes in float4 units
#define N4_K   (NQ * INP_DIM / 4)              // 8388608
#define N4_MEM (NUM_MEM * MEM_DIM / 4)         // 524288
#define N4_W   (INP_DIM * MEM_DIM / 4)         // 131072
#define N4_TOT (N4_K + N4_MEM + 2 * N4_W + NQ / 4)

__global__ void fused_convert_kernel(const float* __restrict__ k, __half* __restrict__ kh,
                                     const float* __restrict__ mem, __half* __restrict__ memh,
                                     const float* __restrict__ fkw, __half* __restrict__ fkwh,
                                     const float* __restrict__ fvw, __half* __restrict__ fvwh,
                                     float* __restrict__ rowsum) {
    int i = blockIdx.x * blockDim.x + threadIdx.x;
    const float* in;
    __half* out;
    if (i < N4_K) {
        in = k; out = kh;
    } else if (i < N4_K + N4_MEM) {
        i -= N4_K; in = mem; out = memh;
    } else if (i < N4_K + N4_MEM + N4_W) {
        i -= N4_K + N4_MEM; in = fkw; out = fkwh;
    } else if (i < N4_K + N4_MEM + 2 * N4_W) {
        i -= N4_K + N4_MEM + N4_W; in = fvw; out = fvwh;
    } else {
        i -= N4_K + N4_MEM + 2 * N4_W;
        if (i < NQ / 4) {
            float4 z = make_float4(0.f, 0.f, 0.f, 0.f);
            reinterpret_cast<float4*>(rowsum)[i] = z;
        }
        return;
    }
    float4 v = reinterpret_cast<const float4*>(in)[i];
    __half2* o = reinterpret_cast<__half2*>(out) + (size_t)i * 2;
    o[0] = __floats2half2_rn(v.x, v.y);
    o[1] = __floats2half2_rn(v.z, v.w);
}

// shared tile geometry (R7 winner): BM=128, BN=256, BK=64, 4-stage
#define BBM 128
#define BBN 256
#define BBK 64
#define BSTAGES 4
#define BA_BYTES (BBM * 128)                 // 16 KB
#define BB_BYTES (BBN * 128)                 // 32 KB
#define BSTAGE_BYTES (BA_BYTES + BB_BYTES)   // 48 KB
#define BDSMEM (BSTAGES * BSTAGE_BYTES)      // 192 KB

// =====================================================================
// Big fp16 TN GEMM (mma.sync, f32 accum): C[M,N] = A[M,K] * B[N,K]^T
// R7 winner structure. mode 1: fp32 store scaled by 1/rs[row] (if rs).
// mode 2: E = exp(C) -> fp16 store + atomicAdd per-row sums into rs.
// =====================================================================
__global__ __launch_bounds__(256, 1)
void gemm_big(const __half* __restrict__ A, const __half* __restrict__ B,
              int K, float* __restrict__ rs, int mode, void* __restrict__ Cout, int ldc)
{
    extern __shared__ __align__(128) char dsm[];
    const uint32_t sbase = smem_u32(dsm);

    const int tid  = threadIdx.x;
    const int lane = tid & 31;
    const int warp = tid >> 5;
    const int wm = warp >> 2;       // 0..1
    const int wn = warp & 3;        // 0..3
    const int bm = blockIdx.y * BBM;
    const int bn = blockIdx.x * BBN;

    float acc[4][8][4];
#pragma unroll
    for (int i = 0; i < 4; i++)
#pragma unroll
        for (int j = 0; j < 8; j++)
#pragma unroll
            for (int q = 0; q < 4; q++) acc[i][j][q] = 0.f;

    const int KT = K / BBK;

    auto load_tile = [&](int st, int kt) {
        const uint32_t a_s = sbase + st * BSTAGE_BYTES;
        const uint32_t b_s = a_s + BA_BYTES;
        const int kk = kt * BBK;
#pragma unroll
        for (int g = 0; g < 4; g++) {
            int idx = tid + g * 256;
            int r = idx >> 3, c = idx & 7;
            cp_async16(a_s + r * 128 + ((c ^ (r & 7)) << 4),
                       A + (size_t)(bm + r) * K + kk + c * 8);
        }
#pragma unroll
        for (int g = 0; g < 8; g++) {
            int idx = tid + g * 256;
            int r = idx >> 3, c = idx & 7;
            cp_async16(b_s + r * 128 + ((c ^ (r & 7)) << 4),
                       B + (size_t)(bn + r) * K + kk + c * 8);
        }
        cp_commit();
    };

    load_tile(0, 0);
    load_tile(1, 1);
    load_tile(2, 2);
    load_tile(3, 3);

    for (int kt = 0; kt < KT; ++kt) {
        const int st = kt & 3;
        cp_wait<BSTAGES - 1>();
        __syncthreads();

        const uint32_t a_s = sbase + st * BSTAGE_BYTES;
        const uint32_t b_s = a_s + BA_BYTES;

#pragma unroll
        for (int ks = 0; ks < 4; ++ks) {
            uint32_t a[4][4];
#pragma unroll
            for (int mi = 0; mi < 4; mi++) {
                int row = wm * 64 + mi * 16 + (lane & 15);
                int c = ks * 2 + (lane >> 4);
                uint32_t addr = a_s + row * 128 + ((c ^ (row & 7)) << 4);
                asm volatile("ldmatrix.sync.aligned.m8n8.x4.shared.b16 {%0,%1,%2,%3}, [%4];\n"
                             : "=r"(a[mi][0]), "=r"(a[mi][1]), "=r"(a[mi][2]), "=r"(a[mi][3])
                             : "r"(addr));
            }
            uint32_t b[8][2];
#pragma unroll
            for (int nb = 0; nb < 4; nb++) {
                int row = wn * 64 + nb * 16 + (lane & 7) + ((lane >> 4) << 3);
                int c = ks * 2 + ((lane >> 3) & 1);
                uint32_t addr = b_s + row * 128 + ((c ^ (row & 7)) << 4);
                asm volatile("ldmatrix.sync.aligned.m8n8.x4.shared.b16 {%0,%1,%2,%3}, [%4];\n"
                             : "=r"(b[nb * 2][0]), "=r"(b[nb * 2][1]),
                               "=r"(b[nb * 2 + 1][0]), "=r"(b[nb * 2 + 1][1])
                             : "r"(addr));
            }
#pragma unroll
            for (int mi = 0; mi < 4; mi++)
#pragma unroll
                for (int ni = 0; ni < 8; ni++)
                    asm volatile("mma.sync.aligned.m16n8k16.row.col.f32.f16.f16.f32 "
                                 "{%0,%1,%2,%3}, {%4,%5,%6,%7}, {%8,%9}, {%0,%1,%2,%3};\n"
                                 : "+f"(acc[mi][ni][0]), "+f"(acc[mi][ni][1]),
                                   "+f"(acc[mi][ni][2]), "+f"(acc[mi][ni][3])
                                 : "r"(a[mi][0]), "r"(a[mi][1]), "r"(a[mi][2]), "r"(a[mi][3]),
                                   "r"(b[ni][0]), "r"(b[ni][1]));
        }

        __syncthreads();
        if (kt + BSTAGES < KT) load_tile(st, kt + BSTAGES);
    }

    const int gid = lane >> 2, tg = lane & 3;

    if (mode == 2) {
        __half* C = (__half*)Cout;
#pragma unroll
        for (int mi = 0; mi < 4; mi++) {
            int row = bm + wm * 64 + mi * 16 + gid;
            float s_lo = 0.f, s_hi = 0.f;
#pragma unroll
            for (int ni = 0; ni < 8; ni++) {
                int col = bn + wn * 64 + ni * 8 + tg * 2;
                float e0 = __expf(acc[mi][ni][0]);
                float e1 = __expf(acc[mi][ni][1]);
                float e2 = __expf(acc[mi][ni][2]);
                float e3 = __expf(acc[mi][ni][3]);
                s_lo += e0 + e1;
                s_hi += e2 + e3;
                *reinterpret_cast<__half2*>(&C[(size_t)row * ldc + col]) =
                    __floats2half2_rn(e0, e1);
                *reinterpret_cast<__half2*>(&C[(size_t)(row + 8) * ldc + col]) =
                    __floats2half2_rn(e2, e3);
            }
            s_lo += __shfl_xor_sync(0xffffffffu, s_lo, 1);
            s_lo += __shfl_xor_sync(0xffffffffu, s_lo, 2);
            s_hi += __shfl_xor_sync(0xffffffffu, s_hi, 1);
            s_hi += __shfl_xor_sync(0xffffffffu, s_hi, 2);
            if (tg == 0) {
                atomicAdd(&rs[row], s_lo);
                atomicAdd(&rs[row + 8], s_hi);
            }
        }
    } else {
        float* C = (float*)Cout;
#pragma unroll
        for (int mi = 0; mi < 4; mi++) {
            int row = bm + wm * 64 + mi * 16 + gid;
            float inv_lo = 1.f, inv_hi = 1.f;
            if (rs) {
                inv_lo = 1.f / __ldg(&rs[row]);
                inv_hi = 1.f / __ldg(&rs[row + 8]);
            }
#pragma unroll
            for (int ni = 0; ni < 8; ni++) {
                int col = bn + wn * 64 + ni * 8 + tg * 2;
                C[(size_t)row * ldc + col]           = acc[mi][ni][0] * inv_lo;
                C[(size_t)row * ldc + col + 1]       = acc[mi][ni][1] * inv_lo;
                C[(size_t)(row + 8) * ldc + col]     = acc[mi][ni][2] * inv_hi;
                C[(size_t)(row + 8) * ldc + col + 1] = acc[mi][ni][3] * inv_hi;
            }
        }
    }
}

// ---------------- generic fp16 TN GEMM (mma.sync, f32 acc) for the prep GEMMs ------------
#define GBM 128
#define GBN 128
#define GBK 32
#define SSTR 48

__global__ __launch_bounds__(256)
void gemm_tn(const __half* __restrict__ A, const __half* __restrict__ B,
             int M, int N, int K, const float* __restrict__ bias, int mode,
             void* __restrict__ Cout, int ldc)
{
    __shared__ __half sA[2][GBM * SSTR];
    __shared__ __half sB[2][GBN * SSTR];

    const int tid  = threadIdx.x;
    const int lane = tid & 31;
    const int warp = tid >> 5;
    const int wm = warp >> 1;
    const int wn = warp & 1;
    const int bm = blockIdx.y * GBM;
    const int bn = blockIdx.x * GBN;

    const int c0 = tid, c1 = tid + 256;
    const int r0 = c0 >> 2, cc0 = (c0 & 3) * 8;
    const int r1 = c1 >> 2, cc1 = (c1 & 3) * 8;

    float acc[2][8][4];
#pragma unroll
    for (int i = 0; i < 2; i++)
#pragma unroll
        for (int j = 0; j < 8; j++)
#pragma unroll
            for (int q = 0; q < 4; q++) acc[i][j][q] = 0.f;

    const int KT = K / GBK;
    {
        cp_async16(smem_u32(&sA[0][r0 * SSTR + cc0]), A + (size_t)(bm + r0) * K + cc0);
        cp_async16(smem_u32(&sA[0][r1 * SSTR + cc1]), A + (size_t)(bm + r1) * K + cc1);
        cp_async16(smem_u32(&sB[0][r0 * SSTR + cc0]), B + (size_t)(bn + r0) * K + cc0);
        cp_async16(smem_u32(&sB[0][r1 * SSTR + cc1]), B + (size_t)(bn + r1) * K + cc1);
        cp_commit();
    }

    for (int kt = 0; kt < KT; ++kt) {
        const int buf = kt & 1;
        if (kt + 1 < KT) {
            const int k0 = (kt + 1) * GBK;
            const int nb = buf ^ 1;
            cp_async16(smem_u32(&sA[nb][r0 * SSTR + cc0]), A + (size_t)(bm + r0) * K + k0 + cc0);
            cp_async16(smem_u32(&sA[nb][r1 * SSTR + cc1]), A + (size_t)(bm + r1) * K + k0 + cc1);
            cp_async16(smem_u32(&sB[nb][r0 * SSTR + cc0]), B + (size_t)(bn + r0) * K + k0 + cc0);
            cp_async16(smem_u32(&sB[nb][r1 * SSTR + cc1]), B + (size_t)(bn + r1) * K + k0 + cc1);
            cp_commit();
            cp_wait<1>();
        } else {
            cp_wait<0>();
        }
        __syncthreads();

#pragma unroll
        for (int ks = 0; ks < 2; ++ks) {
            uint32_t a[2][4];
#pragma unroll
            for (int mi = 0; mi < 2; mi++) {
                uint32_t addr = smem_u32(&sA[buf][(wm * 32 + mi * 16 + (lane & 15)) * SSTR
                                                  + ks * 16 + (lane >> 4) * 8]);
                asm volatile("ldmatrix.sync.aligned.m8n8.x4.shared.b16 {%0,%1,%2,%3}, [%4];\n"
                             : "=r"(a[mi][0]), "=r"(a[mi][1]), "=r"(a[mi][2]), "=r"(a[mi][3])
                             : "r"(addr));
            }
            uint32_t b[8][2];
#pragma unroll
            for (int nb2 = 0; nb2 < 4; nb2++) {
                int nrow = wn * 64 + nb2 * 16 + (lane & 7) + ((lane >> 4) << 3);
                int kcol = ks * 16 + (((lane >> 3) & 1) << 3);
                uint32_t addr = smem_u32(&sB[buf][nrow * SSTR + kcol]);
                asm volatile("ldmatrix.sync.aligned.m8n8.x4.shared.b16 {%0,%1,%2,%3}, [%4];\n"
                             : "=r"(b[nb2 * 2][0]), "=r"(b[nb2 * 2][1]),
                               "=r"(b[nb2 * 2 + 1][0]), "=r"(b[nb2 * 2 + 1][1])
                             : "r"(addr));
            }
#pragma unroll
            for (int mi = 0; mi < 2; mi++)
#pragma unroll
                for (int ni = 0; ni < 8; ni++)
                    asm volatile("mma.sync.aligned.m16n8k16.row.col.f32.f16.f16.f32 "
                                 "{%0,%1,%2,%3}, {%4,%5,%6,%7}, {%8,%9}, {%0,%1,%2,%3};\n"
                                 : "+f"(acc[mi][ni][0]), "+f"(acc[mi][ni][1]),
                                   "+f"(acc[mi][ni][2]), "+f"(acc[mi][ni][3])
                                 : "r"(a[mi][0]), "r"(a[mi][1]), "r"(a[mi][2]), "r"(a[mi][3]),
                                   "r"(b[ni][0]), "r"(b[ni][1]));
        }
        __syncthreads();
    }

    const int gid = lane >> 2, tg = lane & 3;
#pragma unroll
    for (int mi = 0; mi < 2; mi++) {
#pragma unroll
        for (int ni = 0; ni < 8; ni++) {
            int row = bm + wm * 32 + mi * 16 + gid;
            int col = bn + wn * 64 + ni * 8 + tg * 2;
            float v0 = acc[mi][ni][0], v1 = acc[mi][ni][1];
            float v2 = acc[mi][ni][2], v3 = acc[mi][ni][3];
            if (mode == 1) {
                float* C = (float*)Cout;
                float b0 = bias ? bias[col] : 0.f;
                float b1 = bias ? bias[col + 1] : 0.f;
                C[(size_t)row * ldc + col]           = v0 + b0;
                C[(size_t)row * ldc + col + 1]       = v1 + b1;
                C[(size_t)(row + 8) * ldc + col]     = v2 + b0;
                C[(size_t)(row + 8) * ldc + col + 1] = v3 + b1;
            } else {  // mode 2: relu(C + bias), transposed fp16 store
                __half* C = (__half*)Cout;
                float b0 = bias[col], b1 = bias[col + 1];
                C[(size_t)col * ldc + row]           = __float2half(fmaxf(v0 + b0, 0.f));
                C[(size_t)(col + 1) * ldc + row]     = __float2half(fmaxf(v1 + b1, 0.f));
                C[(size_t)col * ldc + row + 8]       = __float2half(fmaxf(v2 + b0, 0.f));
                C[(size_t)(col + 1) * ldc + row + 8] = __float2half(fmaxf(v3 + b1, 0.f));
            }
        }
    }
}

// ---------------- block reduction helpers ----------------
__device__ __forceinline__ float block_reduce_max(float v, float* sred) {
#pragma unroll
    for (int o = 16; o > 0; o >>= 1) v = fmaxf(v, __shfl_xor_sync(0xffffffffu, v, o));
    if ((threadIdx.x & 31) == 0) sred[threadIdx.x >> 5] = v;
    __syncthreads();
    if (threadIdx.x == 0) {
        float m = sred[0];
        for (int w = 1; w < (int)(blockDim.x >> 5); w++) m = fmaxf(m, sred[w]);
        sred[0] = m;
    }
    __syncthreads();
    float r = sred[0];
    __syncthreads();
    return r;
}
__device__ __forceinline__ float block_reduce_sum(float v, float* sred) {
#pragma unroll
    for (int o = 16; o > 0; o >>= 1) v += __shfl_xor_sync(0xffffffffu, v, o);
    if ((threadIdx.x & 31) == 0) sred[threadIdx.x >> 5] = v;
    __syncthreads();
    if (threadIdx.x == 0) {
        float s = sred[0];
        for (int w = 1; w < (int)(blockDim.x >> 5); w++) s += sred[w];
        sred[0] = s;
    }
    __syncthreads();
    float r = sred[0];
    __syncthreads();
    return r;
}

// ---------------- softmax: fp32 logits row -> fp16 (key derivation) ----------------
__global__ __launch_bounds__(256)
void softmax_f32_f16(const float* __restrict__ in, __half* __restrict__ out, int ncol) {
    __shared__ float sred[8];
    const float* x = in + (size_t)blockIdx.x * ncol;
    __half* o = out + (size_t)blockIdx.x * ncol;
    float m = -1e30f;
    for (int i = threadIdx.x; i < ncol; i += blockDim.x) m = fmaxf(m, x[i]);
    m = block_reduce_max(m, sred);
    float s = 0.f;
    for (int i = threadIdx.x; i < ncol; i += blockDim.x) s += __expf(x[i] - m);
    s = block_reduce_sum(s, sred);
    float inv = 1.f / s;
    for (int i = threadIdx.x; i < ncol; i += blockDim.x)
        o[i] = __float2half(__expf(x[i] - m) * inv);
}

// ---------------- launch ----------------
extern "C" void kernel_launch(void* const* d_in, const int* in_sizes, int n_in,
                              void* d_out, int out_size) {
    const float* k    = (const float*)d_in[0];
    const float* mem  = (const float*)d_in[1];
    const float* fk_w = (const float*)d_in[2];
    const float* fk_b = (const float*)d_in[3];
    const float* fv_w = (const float*)d_in[4];
    const float* fv_b = (const float*)d_in[5];
    float* out = (float*)d_out;

    void *p_kh, *p_memh, *p_fkw, *p_fvw, *p_keylog, *p_key, *p_valT, *p_S, *p_rs;
    cudaGetSymbolAddress(&p_kh, g_kh);
    cudaGetSymbolAddress(&p_memh, g_memh);
    cudaGetSymbolAddress(&p_fkw, g_fkw);
    cudaGetSymbolAddress(&p_fvw, g_fvw);
    cudaGetSymbolAddress(&p_keylog, g_keylog);
    cudaGetSymbolAddress(&p_key, g_key);
    cudaGetSymbolAddress(&p_valT, g_valT);
    cudaGetSymbolAddress(&p_S, g_S);
    cudaGetSymbolAddress(&p_rs, g_rowsum);

    __half* kh     = (__half*)p_kh;
    __half* memh   = (__half*)p_memh;
    __half* fkwh   = (__half*)p_fkw;
    __half* fvwh   = (__half*)p_fvw;
    float*  keylog = (float*)p_keylog;
    __half* keyh   = (__half*)p_key;
    __half* valT   = (__half*)p_valT;
    __half* S      = (__half*)p_S;
    float*  rowsum = (float*)p_rs;

    cudaFuncSetAttribute(gemm_big, cudaFuncAttributeMaxDynamicSharedMemorySize, BDSMEM);

    // all converts + rowsum zero, one launch
    fused_convert_kernel<<<(N4_TOT + 255) / 256, 256>>>(k, kh, mem, memh,
                                                        fk_w, fkwh, fv_w, fvwh, rowsum);

    // prep: key logits (fp32 + bias), val = relu -> transposed fp16
    {
        dim3 grid(INP_DIM / GBN, NUM_MEM / GBM);
        gemm_tn<<<grid, 256>>>(memh, fkwh, NUM_MEM, INP_DIM, MEM_DIM, fk_b, 1, keylog, INP_DIM);
        gemm_tn<<<grid, 256>>>(memh, fvwh, NUM_MEM, INP_DIM, MEM_DIM, fv_b, 2, valT, NUM_MEM);
    }
    softmax_f32_f16<<<NUM_MEM, 256>>>(keylog, keyh, INP_DIM);

    // E = exp(k @ key^T) [32768, 4096] + row sums (f32 accum)
    {
        dim3 grid(NUM_MEM / BBN, NQ / BBM);   // (16, 256)
        gemm_big<<<grid, 256, BDSMEM>>>(kh, keyh, INP_DIM, rowsum, 2, S, NUM_MEM);
    }

    // out = (E @ valT^T) / rowsum   [32768, 1024]  (f32 accum)
    {
        dim3 grid(INP_DIM / BBN, NQ / BBM);   // (4, 256)
        gemm_big<<<grid, 256, BDSMEM>>>(S, valT, NUM_MEM, rowsum, 1, out, INP_DIM);
    }
}